// round 6
// baseline (speedup 1.0000x reference)
#include <cuda_runtime.h>
#include <cuda_fp8.h>
#include <cstdint>

#define B_   4
#define H_   32
#define W_   32
#define C_   64
#define F_   128
#define NF   8
#define KC   (C_ * NF)       // 512 fp8 bytes per kernel position
#define KTOT (9 * KC)        // 4608
#define HP   34
#define WP   34
#define NPIX (B_ * H_ * W_)  // 4096
#define NOUT (NPIX * F_)     // 524288

#define LDB  144             // smem row stride in BYTES

// Scratch (device globals — no allocation)
__device__ __align__(16) uint8_t g_Xf[B_ * HP * WP * KC]; // ~2.4 MB e4m3
__device__ __align__(16) uint8_t g_Wt[F_ * KTOT];         // ~0.6 MB e4m3
__device__ __align__(16) float   g_Part[3][NOUT];         // 6 MB split-K partials

__device__ __forceinline__ int load_bits(const int* bp) {
    if (bp == nullptr) return 4;
    int b = bp[0];
    if (b < 1 || b > 30) b = (int)__int_as_float(b);
    if (b < 1 || b > 30) b = 4;
    return b;
}
__device__ __forceinline__ uint8_t to_e4m3(float f) {
    return (uint8_t)__nv_cvt_float_to_fp8(f, __NV_SATFINITE, __NV_E4M3);
}

#define FEAT_TOTAL (B_ * HP * WP * C_)   // 295936
#define WT_TOTAL   (9 * C_ * F_)         // 73728
#define PREP_TOTAL (FEAT_TOTAL + WT_TOTAL)

// ---------------------------------------------------------------------------
// Prep: feature expand (e4m3) + weight expand (e4m3).
// ---------------------------------------------------------------------------
__global__ void prep_kernel(const float* __restrict__ x, const float* __restrict__ kern,
                            const int* __restrict__ bitsPtr) {
    int idx = blockIdx.x * blockDim.x + threadIdx.x;
    if (idx >= PREP_TOTAL) return;
    int bits = load_bits(bitsPtr);

    if (idx < FEAT_TOTAL) {
        int c  = idx & (C_ - 1);
        int r  = idx >> 6;
        int wp = r % WP; r /= WP;
        int hp = r % HP;
        int b  = r / HP;

        int xi = 0;
        if (hp >= 1 && hp <= H_ && wp >= 1 && wp <= W_)
            xi = (int)x[(((b * H_) + (hp - 1)) * W_ + (wp - 1)) * C_ + c];

        uint64_t pack = 0;
#pragma unroll
        for (int m = 1; m <= 8; m++)
            pack |= (uint64_t)to_e4m3((float)((xi * m) >> bits)) << (8 * (m - 1));
        reinterpret_cast<uint64_t*>(g_Xf)[idx] = pack;
    } else {
        int i = idx - FEAT_TOTAL;
        int mask = (1 << bits) - 1;
        int f   = i & (F_ - 1);
        int r   = i >> 7;
        int c   = r & (C_ - 1);
        int pos = r >> 6;

        int wi = (int)kern[i];
        int s  = (wi > 0) - (wi < 0);
        int m  = (wi < 0 ? -wi : wi) & mask;

        uint64_t pack = 0;
        if (m >= 1 && m <= 8)
            pack = (uint64_t)(s > 0 ? 0x38u : 0xB8u) << (8 * (m - 1)); // ±1 e4m3
        reinterpret_cast<uint64_t*>(g_Wt)[f * (KTOT / 8) + pos * (KC / 8) + c] = pack;
    }
}

// ---------------------------------------------------------------------------
// Reduce: out = relu(part0 + part1 + part2 + bias), float4 vectorized.
// ---------------------------------------------------------------------------
__global__ void reduce_kernel(float4* __restrict__ out, const float4* __restrict__ bias4) {
    int i = blockIdx.x * blockDim.x + threadIdx.x;
    if (i >= NOUT / 4) return;
    float4 a = ((const float4*)g_Part[0])[i];
    float4 b = ((const float4*)g_Part[1])[i];
    float4 c = ((const float4*)g_Part[2])[i];
    float4 bv = bias4[i & 31];
    float4 o;
    o.x = fmaxf(a.x + b.x + c.x + bv.x, 0.f);
    o.y = fmaxf(a.y + b.y + c.y + bv.y, 0.f);
    o.z = fmaxf(a.z + b.z + c.z + bv.z, 0.f);
    o.w = fmaxf(a.w + b.w + c.w + bv.w, 0.f);
    out[i] = o;
}

// ---------------------------------------------------------------------------
// FP8 GEMM: block 64(M) x 128(N), 8 warps 2x4 (warp 32x32). Grid (64, 3).
// Each CTA: K = 3 positions x 512 = 1536 bytes, 12 double-buffered 128B slabs.
// Epilogue: smem-staged coalesced stores to partial buffer (NO atomics).
// ---------------------------------------------------------------------------
__device__ __forceinline__ void mma_e4m3(float c[4], const uint32_t a[4], const uint32_t b0,
                                         const uint32_t b1) {
    asm volatile(
        "mma.sync.aligned.m16n8k32.row.col.f32.e4m3.e4m3.f32 "
        "{%0,%1,%2,%3}, {%4,%5,%6,%7}, {%8,%9}, {%0,%1,%2,%3};\n"
        : "+f"(c[0]), "+f"(c[1]), "+f"(c[2]), "+f"(c[3])
        : "r"(a[0]), "r"(a[1]), "r"(a[2]), "r"(a[3]), "r"(b0), "r"(b1));
}
__device__ __forceinline__ void ldsm_x4(uint32_t r[4], uint32_t addr) {
    asm volatile("ldmatrix.sync.aligned.m8n8.x4.shared.b16 {%0,%1,%2,%3}, [%4];"
                 : "=r"(r[0]), "=r"(r[1]), "=r"(r[2]), "=r"(r[3]) : "r"(addr));
}
__device__ __forceinline__ void cp16(uint32_t smemAddr, const void* gmem) {
    asm volatile("cp.async.cg.shared.global [%0], [%1], 16;" :: "r"(smemAddr), "l"(gmem));
}

#define ASLAB (64 * LDB)                 // 9216 B per A buffer
#define BSLAB (128 * LDB)                // 18432 B per B buffer
#define SMEMB (2 * ASLAB + 2 * BSLAB)    // 55296 B

__global__ __launch_bounds__(256, 3) void gemm_kernel() {
    extern __shared__ uint8_t sm[];
    uint8_t* As = sm;               // [2][64][LDB]
    uint8_t* Bs = sm + 2 * ASLAB;   // [2][128][LDB]

    const int tid = threadIdx.x;
    const int pg  = blockIdx.y;          // pos-group 0..2
    const int p0  = blockIdx.x * 64;

    const int cr = tid >> 3;             // 0..31
    const int cc = tid & 7;              // 16B chunk within 128B slab row

    // pixel decomposition for the 2 A rows this thread loads
    int pixA[2];
#pragma unroll
    for (int ps = 0; ps < 2; ps++) {
        int p = p0 + cr + ps * 32;
        int bb = p >> 10, hh = (p >> 5) & 31, ww = p & 31;
        pixA[ps] = (bb * HP + hh) * WP + ww;   // di,dj added per stage
    }

    uint32_t aDst[2], bDst[4];
#pragma unroll
    for (int ps = 0; ps < 2; ps++)
        aDst[ps] = (uint32_t)__cvta_generic_to_shared(As + (cr + ps * 32) * LDB + cc * 16);
#pragma unroll
    for (int ps = 0; ps < 4; ps++)
        bDst[ps] = (uint32_t)__cvta_generic_to_shared(Bs + (cr + ps * 32) * LDB + cc * 16);

    // stage s (0..11): pos = pg*3 + s/4, k0 = (s%4)*128
    auto issue_stage = [&](int s) {
        const int pl  = s >> 2;
        const int pos = pg * 3 + pl;
        const int di  = pos / 3, dj = pos - di * 3;
        const int k0  = (s & 3) * 128;
        const int buf = s & 1;
#pragma unroll
        for (int ps = 0; ps < 2; ps++) {
            const uint8_t* src = g_Xf + (pixA[ps] + di * WP + dj) * KC + k0 + cc * 16;
            cp16(aDst[ps] + buf * ASLAB, src);
        }
#pragma unroll
        for (int ps = 0; ps < 4; ps++) {
            const uint8_t* src = g_Wt + (cr + ps * 32) * KTOT + pos * KC + k0 + cc * 16;
            cp16(bDst[ps] + buf * BSLAB, src);
        }
        asm volatile("cp.async.commit_group;");
    };

    // fragment addressing
    const int wa = tid >> 5, lane = tid & 31;
    const int wm = wa & 1, wn = wa >> 1;
    const int fRow  = lane & 15;
    const int fColB = (lane >> 4) << 4;

    float acc[2][4][4];
#pragma unroll
    for (int mi = 0; mi < 2; mi++)
#pragma unroll
        for (int j = 0; j < 4; j++)
#pragma unroll
            for (int e = 0; e < 4; e++) acc[mi][j][e] = 0.0f;

    issue_stage(0);

#pragma unroll 1
    for (int s = 0; s < 12; s++) {
        const int cur = s & 1;
        if (s < 11) {
            issue_stage(s + 1);
            asm volatile("cp.async.wait_group 1;");
        } else {
            asm volatile("cp.async.wait_group 0;");
        }
        __syncthreads();

        const uint8_t* Ab = As + cur * ASLAB;
        const uint8_t* Bb = Bs + cur * BSLAB;
#pragma unroll
        for (int kk = 0; kk < 4; kk++) {
            const int kcB = kk * 32;
            uint32_t a[2][4], b[2][4];
#pragma unroll
            for (int mi = 0; mi < 2; mi++) {
                uint32_t ad = (uint32_t)__cvta_generic_to_shared(
                    Ab + (wm * 32 + mi * 16 + fRow) * LDB + kcB + fColB);
                ldsm_x4(a[mi], ad);
            }
#pragma unroll
            for (int ni = 0; ni < 2; ni++) {
                uint32_t bd = (uint32_t)__cvta_generic_to_shared(
                    Bb + (wn * 32 + ni * 16 + fRow) * LDB + kcB + fColB);
                ldsm_x4(b[ni], bd);
            }
#pragma unroll
            for (int mi = 0; mi < 2; mi++)
#pragma unroll
                for (int j = 0; j < 4; j++)
                    mma_e4m3(acc[mi][j], a[mi], b[j >> 1][j & 1], b[j >> 1][(j & 1) + 2]);
        }
        __syncthreads();
    }

    // ---- epilogue: stage 64x128 f32 tile in smem, coalesced STG.128 ----
    float* S = (float*)sm;   // 32 KB < SMEMB
    const int g = lane >> 2, t4 = lane & 3;
#pragma unroll
    for (int mi = 0; mi < 2; mi++) {
        int r0 = wm * 32 + mi * 16 + g;
#pragma unroll
        for (int j = 0; j < 4; j++) {
            int ccol = wn * 32 + j * 8 + t4 * 2;
            *(float2*)&S[r0 * F_ + ccol]       = make_float2(acc[mi][j][0], acc[mi][j][1]);
            *(float2*)&S[(r0 + 8) * F_ + ccol] = make_float2(acc[mi][j][2], acc[mi][j][3]);
        }
    }
    __syncthreads();

    float4* dst = (float4*)(g_Part[pg] + p0 * F_);
    const float4* src = (const float4*)S;
#pragma unroll
    for (int i = 0; i < (64 * F_ / 4) / 256; i++)
        dst[tid + i * 256] = src[tid + i * 256];
}

// ---------------------------------------------------------------------------
extern "C" void kernel_launch(void* const* d_in, const int* in_sizes, int n_in,
                              void* d_out, int out_size) {
    const float* x    = (const float*)d_in[0];
    const float* kern = (const float*)d_in[1];
    const float* bias = (const float*)d_in[2];
    const int*   bits = (n_in >= 4) ? (const int*)d_in[3] : nullptr;
    float* out = (float*)d_out;

    static int smemSet = 0;
    if (!smemSet) {
        cudaFuncSetAttribute(gemm_kernel, cudaFuncAttributeMaxDynamicSharedMemorySize, SMEMB);
        smemSet = 1;
    }

    prep_kernel<<<(PREP_TOTAL + 255) / 256, 256>>>(x, kern, bits);
    dim3 gg(NPIX / 64, 3);
    gemm_kernel<<<gg, 256, SMEMB>>>();
    reduce_kernel<<<(NOUT / 4 + 255) / 256, 256>>>((float4*)out, (const float4*)bias);
}